// round 17
// baseline (speedup 1.0000x reference)
#include <cuda_runtime.h>
#include <cuda_fp16.h>

#define NEDGE 8192
#define DD    256
#define SPLITK 32

typedef unsigned int u32;

// ---------------- scratch (device globals; no allocation allowed) ----------
__device__ __align__(16) half g_X16[NEDGE * DD];
__device__ __align__(16) half g_e16[2][NEDGE * DD];
__device__ __align__(16) half g_W116[DD * DD], g_W216[DD * DD];
__device__ __align__(16) half g_W3a16[DD * DD];
__device__ __align__(16) half g_P16[2][DD * DD];
__device__ __align__(16) half g_MpartH[2][SPLITK][DD * DD];

// ---------------- helpers ---------------------------------------------------
__device__ __forceinline__ void cpa16(void* dst, const void* src) {
    unsigned s = (unsigned)__cvta_generic_to_shared(dst);
    asm volatile("cp.async.cg.shared.global [%0], [%1], 16;" :: "r"(s), "l"(src));
}
__device__ __forceinline__ void cpa_commit() { asm volatile("cp.async.commit_group;"); }
__device__ __forceinline__ void cpa_wait0()  { asm volatile("cp.async.wait_group 0;"); }
__device__ __forceinline__ void cpa_wait1()  { asm volatile("cp.async.wait_group 1;"); }

__device__ __forceinline__ unsigned saddr(const void* p) {
    return (unsigned)__cvta_generic_to_shared(p);
}
__device__ __forceinline__ void ldsm_x4(u32* r, unsigned a) {
    asm volatile("ldmatrix.sync.aligned.m8n8.x4.shared.b16 {%0,%1,%2,%3}, [%4];"
        : "=r"(r[0]), "=r"(r[1]), "=r"(r[2]), "=r"(r[3]) : "r"(a));
}
__device__ __forceinline__ void ldsm_x4_t(u32* r, unsigned a) {
    asm volatile("ldmatrix.sync.aligned.m8n8.x4.trans.shared.b16 {%0,%1,%2,%3}, [%4];"
        : "=r"(r[0]), "=r"(r[1]), "=r"(r[2]), "=r"(r[3]) : "r"(a));
}
__device__ __forceinline__ void mma_f16(float* d, const u32* a, const u32* b) {
    asm volatile(
        "mma.sync.aligned.m16n8k16.row.col.f32.f16.f16.f32 "
        "{%0,%1,%2,%3}, {%4,%5,%6,%7}, {%8,%9}, {%0,%1,%2,%3};"
        : "+f"(d[0]), "+f"(d[1]), "+f"(d[2]), "+f"(d[3])
        : "r"(a[0]), "r"(a[1]), "r"(a[2]), "r"(a[3]), "r"(b[0]), "r"(b[1]));
}

// ===========================================================================
// k_cvt: X, W1, W2, W3a -> single fp16. grid 2240 x 256.
// ===========================================================================
__global__ void k_cvt(const float4* __restrict__ X4, const float4* __restrict__ W14,
                      const float4* __restrict__ W24, const float4* __restrict__ W34)
{
    const int idx = blockIdx.x * 256 + threadIdx.x;
    float4 v;
    half* dst;
    size_t o;
    if (idx < 524288) {
        v = X4[idx];
        dst = g_X16;
        o = (size_t)idx * 4;
    } else {
        const int w = idx - 524288;
        const int which = w >> 14;
        const int off4 = w & 16383;
        v = (which == 0) ? W14[off4] : (which == 1) ? W24[off4] : W34[off4];
        dst = (which == 0) ? g_W116 : (which == 1) ? g_W216 : g_W3a16;
        o = (size_t)off4 * 4;
    }
    half2 a; a.x = __float2half_rn(v.x); a.y = __float2half_rn(v.y);
    half2 b; b.x = __float2half_rn(v.z); b.y = __float2half_rn(v.w);
    *reinterpret_cast<half2*>(dst + o)     = a;
    *reinterpret_cast<half2*>(dst + o + 2) = b;
}

// ===========================================================================
// Core: multi-pass fp16 MMA GEMM. Block tile 128x128, 8 warps (2m x 4n),
// warp tile 64x32, k-tile 64, 3-stage cp.async ring. smem 107520 B.
// ===========================================================================
#define AS_ELEM(b, r, c) sAs[(b) * 9216 + (r) * 72 + (c)]
#define BS_ELEM(b, r, c) sBs[(b) * 8704 + (r) * 136 + (c)]

template <int NPASS>
__device__ __forceinline__ void mma_core_rowA(
    const half* const* Ap, const half* const* Bp,
    int rowBase, int colBase, float (&acc)[4][4][4])
{
    extern __shared__ __align__(16) char sm_raw[];
    half* sAs = (half*)sm_raw;
    half* sBs = (half*)(sm_raw + 55296);

    const int tid = threadIdx.x;
    const int lane = tid & 31, w = tid >> 5;
    const int m0w = (w >> 2) * 64, n0w = (w & 3) * 32;

    auto prefetch = [&](int it, int bufn) {
        const int pass = it >> 2;
        const int k0 = (it & 3) * 64;
        const half* __restrict__ A = Ap[pass];
        const half* __restrict__ B = Bp[pass];
#pragma unroll
        for (int i = 0; i < 4; ++i) {
            const int ca = tid + 256 * i;               // A: 128 rows x 64 k
            const int ar = ca >> 3, ao = (ca & 7) * 8;
            cpa16(&AS_ELEM(bufn, ar, ao), A + (size_t)(rowBase + ar) * DD + k0 + ao);
            const int cb = tid + 256 * i;               // B: 64 k x 128 n
            const int br = cb >> 4, bo = (cb & 15) * 8;
            cpa16(&BS_ELEM(bufn, br, bo), B + (size_t)(k0 + br) * DD + colBase + bo);
        }
        cpa_commit();
    };

    const int t = lane >> 3;
    const int aro = (t & 1) * 8 + (lane & 7);
    const int aco = (t >> 1) * 8;
    const int bro2 = (lane & 7) + ((lane >> 3) & 1) * 8;
    const int bco2 = (lane >> 4) * 8;

    constexpr int NIT = NPASS * 4;
    prefetch(0, 0);
    prefetch(1, 1);
    for (int it = 0; it < NIT; ++it) {
        cpa_wait1();
        __syncthreads();
        if (it + 2 < NIT) prefetch(it + 2, (it + 2) % 3);
        else cpa_commit();   // keep wait-group arithmetic exact
        const int buf = it % 3;
#pragma unroll
        for (int ki = 0; ki < 4; ++ki) {
            u32 a[4][4], bq[2][4];
#pragma unroll
            for (int mi = 0; mi < 4; ++mi)
                ldsm_x4(a[mi], saddr(&AS_ELEM(buf, m0w + mi * 16 + aro, ki * 16 + aco)));
#pragma unroll
            for (int nj = 0; nj < 2; ++nj)
                ldsm_x4_t(bq[nj], saddr(&BS_ELEM(buf, ki * 16 + bro2, n0w + nj * 16 + bco2)));
#pragma unroll
            for (int mi = 0; mi < 4; ++mi)
#pragma unroll
                for (int ni = 0; ni < 4; ++ni)
                    mma_f16(acc[mi][ni], a[mi], &bq[ni >> 1][(ni & 1) * 2]);
        }
    }
}

// ===========================================================================
// k_e_mma: e_z = relu(X16 @ W16_z + b_z) -> fp16. 1 pass. grid (2, 64, 2).
// ===========================================================================
__global__ void __launch_bounds__(256, 2)
k_e_mma(const float* __restrict__ b1, const float* __restrict__ b2)
{
    const int z = blockIdx.z;
    const half* Ap[1] = {g_X16};
    const half* Bp[1] = {z ? g_W216 : g_W116};
    const float* __restrict__ bias = z ? b2 : b1;
    half* __restrict__ E = g_e16[z];

    const int rowBase = blockIdx.y * 128, colBase = blockIdx.x * 128;
    float acc[4][4][4] = {};
    mma_core_rowA<1>(Ap, Bp, rowBase, colBase, acc);

    const int lane = threadIdx.x & 31, w = threadIdx.x >> 5;
    const int m0w = (w >> 2) * 64, n0w = (w & 3) * 32;
    const int r_l = lane >> 2, c_l = (lane & 3) * 2;
#pragma unroll
    for (int mi = 0; mi < 4; ++mi)
#pragma unroll
        for (int ni = 0; ni < 4; ++ni) {
            const int col = colBase + n0w + ni * 8 + c_l;
            const float2 bb = *(const float2*)&bias[col];
#pragma unroll
            for (int h = 0; h < 2; ++h) {
                const int r = rowBase + m0w + mi * 16 + r_l + h * 8;
                half2 v;
                v.x = __float2half_rn(fmaxf(acc[mi][ni][h * 2 + 0] + bb.x, 0.f));
                v.y = __float2half_rn(fmaxf(acc[mi][ni][h * 2 + 1] + bb.y, 0.f));
                *reinterpret_cast<half2*>(&E[(size_t)r * DD + col]) = v;
            }
        }
}

// ===========================================================================
// k_mpart_mma: split-K partials of M_z = e16_zᵀ @ X16. 1 pass, NIT = 4.
// fp16 partials out. grid (2, 2, 64) x 256.
// ===========================================================================
#define ES_ELEM(b, r, c) sEs[(b) * 8704 + (r) * 136 + (c)]
#define XS_ELEM(b, r, c) sXs[(b) * 8704 + (r) * 136 + (c)]

__global__ void __launch_bounds__(256, 2)
k_mpart_mma()
{
    const int mat = blockIdx.z >> 5, split = blockIdx.z & 31;
    const half* __restrict__ E = g_e16[mat];
    half* __restrict__ Cp = g_MpartH[mat][split];

    extern __shared__ __align__(16) char sm_raw[];
    half* sEs = (half*)sm_raw;
    half* sXs = (half*)(sm_raw + 52224);

    const int tid = threadIdx.x;
    const int lane = tid & 31, w = tid >> 5;
    const int m0w = (w >> 2) * 64, n0w = (w & 3) * 32;
    const int mBase = blockIdx.y * 128, nBase = blockIdx.x * 128;
    const int i0 = split * (NEDGE / SPLITK);   // 256-edge chunk

    auto prefetch = [&](int it, int bufn) {
        const int e0 = i0 + it * 64;
#pragma unroll
        for (int i = 0; i < 4; ++i) {
            const int c = tid + 256 * i;                // 64 rows x 128 cols
            const int r = c >> 4, o = (c & 15) * 8;
            cpa16(&ES_ELEM(bufn, r, o), E + (size_t)(e0 + r) * DD + mBase + o);
            cpa16(&XS_ELEM(bufn, r, o), g_X16 + (size_t)(e0 + r) * DD + nBase + o);
        }
        cpa_commit();
    };

    const int t = lane >> 3;
    const int akro = (t >> 1) * 8 + (lane & 7);
    const int amco = (t & 1) * 8;
    const int bro2 = (lane & 7) + ((lane >> 3) & 1) * 8;
    const int bco2 = (lane >> 4) * 8;

    float acc[4][4][4] = {};
    prefetch(0, 0);
    prefetch(1, 1);
    for (int it = 0; it < 4; ++it) {
        cpa_wait1();
        __syncthreads();
        if (it + 2 < 4) prefetch(it + 2, (it + 2) % 3);
        else cpa_commit();
        const int buf = it % 3;
#pragma unroll
        for (int ki = 0; ki < 4; ++ki) {
            u32 a[4][4], bq[2][4];
#pragma unroll
            for (int mi = 0; mi < 4; ++mi)
                ldsm_x4_t(a[mi], saddr(&ES_ELEM(buf, ki * 16 + akro, m0w + mi * 16 + amco)));
#pragma unroll
            for (int nj = 0; nj < 2; ++nj)
                ldsm_x4_t(bq[nj], saddr(&XS_ELEM(buf, ki * 16 + bro2, n0w + nj * 16 + bco2)));
#pragma unroll
            for (int mi = 0; mi < 4; ++mi)
#pragma unroll
                for (int ni = 0; ni < 4; ++ni)
                    mma_f16(acc[mi][ni], a[mi], &bq[ni >> 1][(ni & 1) * 2]);
        }
    }

    const int r_l = lane >> 2, c_l = (lane & 3) * 2;
#pragma unroll
    for (int mi = 0; mi < 4; ++mi)
#pragma unroll
        for (int ni = 0; ni < 4; ++ni) {
            const int col = nBase + n0w + ni * 8 + c_l;
#pragma unroll
            for (int h = 0; h < 2; ++h) {
                const int r = mBase + m0w + mi * 16 + r_l + h * 8;
                half2 v;
                v.x = __float2half_rn(acc[mi][ni][h * 2 + 0]);
                v.y = __float2half_rn(acc[mi][ni][h * 2 + 1]);
                *reinterpret_cast<half2*>(&Cp[(size_t)r * DD + col]) = v;
            }
        }
}

// ===========================================================================
// k_p_fused: P_z = ((sum_p MpartH_z,p)/D) @ W3b_z -> fp16 P16.
// Partials read EXACTLY ONCE. grid (8 m-tiles, 2 mats) x 256.
// Per 64-k chunk: each thread owns one 16B (r,k) vector and sums 32 fp16
// planes in fp32 regs (MLP 32, L2-resident) while W3b streams via cp.async.
// Then 32x256 FFMA tile: thread = 2 rows x 16 cols.
// Dynamic smem: Bs 64 x 260 f32 (66560 B) + As 32 x 65 f32 (8320 B) = 74880 B.
// ===========================================================================
__global__ void __launch_bounds__(256)
k_p_fused(const float* __restrict__ W3)
{
    const int mat = blockIdx.y;
    const int mBase = blockIdx.x * 32;
    const float* __restrict__ B = W3 + (size_t)(DD + mat * DD) * DD;

    extern __shared__ __align__(16) char sm_raw[];
    float* Bs = (float*)sm_raw;                 // [64][260]
    float* As = (float*)(sm_raw + 66560);       // [32][65]

    const int tid = threadIdx.x;
    const int rA = tid >> 3;                    // 0..31 (reduce row)
    const int k8 = (tid & 7) * 8;               // 0..56 (reduce col, 8 halves)
    const int r0 = (tid >> 4) * 2;              // FMA rows
    const int c0 = (tid & 15) * 16;             // FMA cols

    float acc0[16] = {}, acc1[16] = {};

    for (int kt = 0; kt < DD; kt += 64) {
        // stream B chunk: 64 x 256 f32 = 4096 float4
#pragma unroll
        for (int i = 0; i < 16; ++i) {
            const int cb = tid + 256 * i;
            const int r = cb >> 6, c = (cb & 63) * 4;
            cpa16(&Bs[r * 260 + c], &B[(size_t)(kt + r) * DD + c]);
        }
        cpa_commit();

        // reduce 32 fp16 planes into fp32 (read-once)
        float s[8] = {};
        const size_t base = (size_t)(mBase + rA) * DD + kt + k8;
#pragma unroll
        for (int p = 0; p < SPLITK; ++p) {
            const uint4 q = *reinterpret_cast<const uint4*>(&g_MpartH[mat][p][base]);
            const half2* h = reinterpret_cast<const half2*>(&q);
#pragma unroll
            for (int j = 0; j < 4; ++j) {
                const float2 f = __half22float2(h[j]);
                s[2 * j + 0] += f.x;
                s[2 * j + 1] += f.y;
            }
        }
        const float sc = 1.0f / DD;
#pragma unroll
        for (int j = 0; j < 8; ++j) As[rA * 65 + k8 + j] = s[j] * sc;

        cpa_wait0();
        __syncthreads();

#pragma unroll
        for (int kk = 0; kk < 64; ++kk) {
            const float a0 = As[(r0 + 0) * 65 + kk];
            const float a1 = As[(r0 + 1) * 65 + kk];
            const float* brow = &Bs[kk * 260 + c0];
#pragma unroll
            for (int j = 0; j < 16; ++j) {
                const float b = brow[j];
                acc0[j] = fmaf(a0, b, acc0[j]);
                acc1[j] = fmaf(a1, b, acc1[j]);
            }
        }
        __syncthreads();
    }

    half* __restrict__ P = g_P16[mat];
    const size_t o0 = (size_t)(mBase + r0 + 0) * DD + c0;
    const size_t o1 = (size_t)(mBase + r0 + 1) * DD + c0;
#pragma unroll
    for (int j = 0; j < 8; ++j) {
        half2 v0; v0.x = __float2half_rn(acc0[2 * j]); v0.y = __float2half_rn(acc0[2 * j + 1]);
        half2 v1; v1.x = __float2half_rn(acc1[2 * j]); v1.y = __float2half_rn(acc1[2 * j + 1]);
        *reinterpret_cast<half2*>(&P[o0 + 2 * j]) = v0;
        *reinterpret_cast<half2*>(&P[o1 + 2 * j]) = v1;
    }
}

// ===========================================================================
// k_final_mma: out = relu(X16@W3a16 + e16_1@P16_1 + e16_2@P16_2 + b3).
// 3 passes. grid (2, 64) x 256.
// ===========================================================================
__global__ void __launch_bounds__(256, 2)
k_final_mma(const float* __restrict__ b3, float* __restrict__ out)
{
    const half* Ap[3] = {g_X16, g_e16[0], g_e16[1]};
    const half* Bp[3] = {g_W3a16, g_P16[0], g_P16[1]};

    const int rowBase = blockIdx.y * 128, colBase = blockIdx.x * 128;
    float acc[4][4][4] = {};
    mma_core_rowA<3>(Ap, Bp, rowBase, colBase, acc);

    const int lane = threadIdx.x & 31, w = threadIdx.x >> 5;
    const int m0w = (w >> 2) * 64, n0w = (w & 3) * 32;
    const int r_l = lane >> 2, c_l = (lane & 3) * 2;
#pragma unroll
    for (int mi = 0; mi < 4; ++mi)
#pragma unroll
        for (int ni = 0; ni < 4; ++ni) {
            const int col = colBase + n0w + ni * 8 + c_l;
            const float2 bb = *(const float2*)&b3[col];
#pragma unroll
            for (int h = 0; h < 2; ++h) {
                const int r = rowBase + m0w + mi * 16 + r_l + h * 8;
                float2 v;
                v.x = fmaxf(acc[mi][ni][h * 2 + 0] + bb.x, 0.f);
                v.y = fmaxf(acc[mi][ni][h * 2 + 1] + bb.y, 0.f);
                *(float2*)&out[(size_t)r * DD + col] = v;
            }
        }
}

// ---------------------------------------------------------------------------
// Inputs (metadata order):
// 0 edge_pred[8192] f32 | 1 edge_corner[8192,2] i64 | 2 all_corners[4096,2] f32
// 3 edge_x[8192,256] f32 | 4 image_x[1024] f32 | 5 W1[256,256] | 6 b1[256]
// 7 W2[256,256] | 8 b2[256] | 9 W3[768,256] | 10 b3[256]
// Output: [8192, 256] f32
// ---------------------------------------------------------------------------
extern "C" void kernel_launch(void* const* d_in, const int* in_sizes, int n_in,
                              void* d_out, int out_size)
{
    (void)in_sizes; (void)n_in; (void)out_size;
    const float* X  = (const float*)d_in[3];
    const float* W1 = (const float*)d_in[5];
    const float* b1 = (const float*)d_in[6];
    const float* W2 = (const float*)d_in[7];
    const float* b2 = (const float*)d_in[8];
    const float* W3 = (const float*)d_in[9];
    const float* b3 = (const float*)d_in[10];
    float* out = (float*)d_out;

    const int SMEM_CORE  = 55296 + 52224;  // 107520 B
    const int SMEM_MPART = 2 * 52224;      // 104448 B
    const int SMEM_P     = 66560 + 8320;   //  74880 B
    cudaFuncSetAttribute(k_e_mma, cudaFuncAttributeMaxDynamicSharedMemorySize, SMEM_CORE);
    cudaFuncSetAttribute(k_final_mma, cudaFuncAttributeMaxDynamicSharedMemorySize, SMEM_CORE);
    cudaFuncSetAttribute(k_mpart_mma, cudaFuncAttributeMaxDynamicSharedMemorySize, SMEM_MPART);
    cudaFuncSetAttribute(k_p_fused, cudaFuncAttributeMaxDynamicSharedMemorySize, SMEM_P);

    k_cvt<<<2240, 256>>>((const float4*)X, (const float4*)W1,
                         (const float4*)W2, (const float4*)W3);
    k_e_mma<<<dim3(2, 64, 2), 256, SMEM_CORE>>>(b1, b2);
    k_mpart_mma<<<dim3(2, 2, 64), 256, SMEM_MPART>>>();
    k_p_fused<<<dim3(8, 2), 256, SMEM_P>>>(W3);
    k_final_mma<<<dim3(2, 64), 256, SMEM_CORE>>>(b3, out);
}